// round 9
// baseline (speedup 1.0000x reference)
#include <cuda_runtime.h>
#include <cstdio>

// AuxIVA: K=4 sources, F=513 freqs, B=4000 frames, 5 iterations.
// d_in[0]=Xr (K,F,B) f32, d_in[1]=Xi (K,F,B) f32.
// Output: float32 (K,F,B) = REAL PART of projected-back demixed signal.
// (out_size = 8,208,000 float32 elements — learned via R7/R8 bisect: the
//  complex64 reference was normalized to float32 => real part.)

#define K_DIM 4
#define F_DIM 513
#define B_DIM 4000
#define FB    (F_DIM * B_DIM)
#define KFB   (K_DIM * F_DIM * B_DIM)      // 8,208,000
#define N_ITER 5
#define NBB2  16                           // ceil(4000/256)

// ---------------- owned staging + scratch ----------------
static __device__ float g_Xr[KFB];                       // 32.8 MB
static __device__ float g_Xi[KFB];                       // 32.8 MB
static __device__ float g_Whr[F_DIM * 16];               // [f][s][c]
static __device__ float g_Whi[F_DIM * 16];
static __device__ float g_part[F_DIM * K_DIM * B_DIM];   // [f][k][b]
static __device__ float g_phi[K_DIM * B_DIM];            // 0.5 / r
static __device__ float g_Vr[64 * F_DIM];                // [k*16+i*4+j][f]
static __device__ float g_Vi[64 * F_DIM];
static __device__ float g_sclr[F_DIM * 4];               // [f][s]
static __device__ float g_scli[F_DIM * 4];

// Solve A u = rhs (4x4 complex) by Gauss-Jordan with conditional-swap partial
// pivoting. Fully unrolled; every index static (no dynamic local indexing).
static __device__ __forceinline__ void solve4(float Ar[4][4], float Ai[4][4],
                                              float ur[4], float ui[4]) {
#pragma unroll
    for (int j = 0; j < 4; j++) {
#pragma unroll
        for (int i = 0; i < 4; i++) {
            if (i > j) {
                float mj = Ar[j][j] * Ar[j][j] + Ai[j][j] * Ai[j][j];
                float mi = Ar[i][j] * Ar[i][j] + Ai[i][j] * Ai[i][j];
                if (mi > mj) {
#pragma unroll
                    for (int c = 0; c < 4; c++) {
                        float tr = Ar[j][c]; Ar[j][c] = Ar[i][c]; Ar[i][c] = tr;
                        float ti = Ai[j][c]; Ai[j][c] = Ai[i][c]; Ai[i][c] = ti;
                    }
                    float tr = ur[j]; ur[j] = ur[i]; ur[i] = tr;
                    float ti = ui[j]; ui[j] = ui[i]; ui[i] = ti;
                }
            }
        }
        float dr = Ar[j][j], di = Ai[j][j];
        float inv = 1.0f / (dr * dr + di * di);
        float pr = dr * inv, pi = -di * inv;
#pragma unroll
        for (int c = 0; c < 4; c++) {
            float ar = Ar[j][c], ai = Ai[j][c];
            Ar[j][c] = ar * pr - ai * pi;
            Ai[j][c] = ar * pi + ai * pr;
        }
        {
            float ar = ur[j], ai = ui[j];
            ur[j] = ar * pr - ai * pi;
            ui[j] = ar * pi + ai * pr;
        }
#pragma unroll
        for (int i = 0; i < 4; i++) {
            if (i != j) {
                float fr = Ar[i][j], fi = Ai[i][j];
#pragma unroll
                for (int c = 0; c < 4; c++) {
                    float ar = Ar[j][c], ai = Ai[j][c];
                    Ar[i][c] -= fr * ar - fi * ai;
                    Ai[i][c] -= fr * ai + fi * ar;
                }
                float ar = ur[j], ai = ui[j];
                ur[i] -= fr * ar - fi * ai;
                ui[i] -= fr * ai + fi * ar;
            }
        }
    }
}

// ---------------- kernels ----------------

static __global__ void k_init() {
    int i = blockIdx.x * blockDim.x + threadIdx.x;
    if (i < F_DIM * 16) {
        int rem = i & 15;      // s*4+c
        g_Whr[i] = (rem == 0 || rem == 5 || rem == 10 || rem == 15) ? 1.f : 0.f;
        g_Whi[i] = 0.f;
    }
}

// part[f][k][b] = |sum_c Wh[f,k,c] X[c,f,b]|^2
static __global__ void k_demix() {
    const int f  = blockIdx.x / NBB2;
    const int bb = blockIdx.x % NBB2;
    const int b  = bb * 256 + threadIdx.x;
    if (b >= B_DIM) return;

    const int base = f * B_DIM + b;
    float xr0 = g_Xr[base],          xi0 = g_Xi[base];
    float xr1 = g_Xr[base + FB],     xi1 = g_Xi[base + FB];
    float xr2 = g_Xr[base + 2 * FB], xi2 = g_Xi[base + 2 * FB];
    float xr3 = g_Xr[base + 3 * FB], xi3 = g_Xi[base + 3 * FB];

#pragma unroll
    for (int s = 0; s < 4; s++) {
        float w0r = g_Whr[f * 16 + s * 4 + 0], w0i = g_Whi[f * 16 + s * 4 + 0];
        float w1r = g_Whr[f * 16 + s * 4 + 1], w1i = g_Whi[f * 16 + s * 4 + 1];
        float w2r = g_Whr[f * 16 + s * 4 + 2], w2i = g_Whi[f * 16 + s * 4 + 2];
        float w3r = g_Whr[f * 16 + s * 4 + 3], w3i = g_Whi[f * 16 + s * 4 + 3];
        float yr = w0r * xr0 - w0i * xi0 + w1r * xr1 - w1i * xi1
                 + w2r * xr2 - w2i * xi2 + w3r * xr3 - w3i * xi3;
        float yi = w0r * xi0 + w0i * xr0 + w1r * xi1 + w1i * xr1
                 + w2r * xi2 + w2i * xr2 + w3r * xi3 + w3i * xr3;
        g_part[f * (K_DIM * B_DIM) + s * B_DIM + b] = yr * yr + yi * yi;
    }
}

// phi[k][b] = 0.5 / sqrt( sum_f part[f][k][b] )
static __global__ void k_phi() {
    int i = blockIdx.x * blockDim.x + threadIdx.x;   // k*B + b
    if (i < K_DIM * B_DIM) {
        float s = 0.f;
        for (int f = 0; f < F_DIM; f++)
            s += g_part[f * (K_DIM * B_DIM) + i];
        g_phi[i] = 0.5f * rsqrtf(s);
    }
}

// V[k,i,j,f]: one block per f, 4 warps (warp = k), shuffle reduce.
static __global__ void k_V() {
    const int f = blockIdx.x;
    const int w = threadIdx.x >> 5;
    const int lane = threadIdx.x & 31;

    float a0 = 0.f, a1 = 0.f, a2 = 0.f, a3 = 0.f;
    float a4 = 0.f, a5 = 0.f, a6 = 0.f, a7 = 0.f;
    float a8 = 0.f, a9 = 0.f, a10 = 0.f, a11 = 0.f;
    float a12 = 0.f, a13 = 0.f, a14 = 0.f, a15 = 0.f;

    for (int b = lane; b < B_DIM; b += 32) {
        const int base = f * B_DIM + b;
        float xr0 = g_Xr[base],          xi0 = g_Xi[base];
        float xr1 = g_Xr[base + FB],     xi1 = g_Xi[base + FB];
        float xr2 = g_Xr[base + 2 * FB], xi2 = g_Xi[base + 2 * FB];
        float xr3 = g_Xr[base + 3 * FB], xi3 = g_Xi[base + 3 * FB];
        float p = g_phi[w * B_DIM + b];

        a0  += p * (xr0 * xr0 + xi0 * xi0);
        a1  += p * (xr1 * xr1 + xi1 * xi1);
        a2  += p * (xr2 * xr2 + xi2 * xi2);
        a3  += p * (xr3 * xr3 + xi3 * xi3);
        a4  += p * (xr0 * xr1 + xi0 * xi1);
        a5  += p * (xi0 * xr1 - xr0 * xi1);
        a6  += p * (xr0 * xr2 + xi0 * xi2);
        a7  += p * (xi0 * xr2 - xr0 * xi2);
        a8  += p * (xr0 * xr3 + xi0 * xi3);
        a9  += p * (xi0 * xr3 - xr0 * xi3);
        a10 += p * (xr1 * xr2 + xi1 * xi2);
        a11 += p * (xi1 * xr2 - xr1 * xi2);
        a12 += p * (xr1 * xr3 + xi1 * xi3);
        a13 += p * (xi1 * xr3 - xr1 * xi3);
        a14 += p * (xr2 * xr3 + xi2 * xi3);
        a15 += p * (xi2 * xr3 - xr2 * xi3);
    }

    for (int off = 16; off > 0; off >>= 1) {
        a0  += __shfl_down_sync(0xffffffffu, a0,  off);
        a1  += __shfl_down_sync(0xffffffffu, a1,  off);
        a2  += __shfl_down_sync(0xffffffffu, a2,  off);
        a3  += __shfl_down_sync(0xffffffffu, a3,  off);
        a4  += __shfl_down_sync(0xffffffffu, a4,  off);
        a5  += __shfl_down_sync(0xffffffffu, a5,  off);
        a6  += __shfl_down_sync(0xffffffffu, a6,  off);
        a7  += __shfl_down_sync(0xffffffffu, a7,  off);
        a8  += __shfl_down_sync(0xffffffffu, a8,  off);
        a9  += __shfl_down_sync(0xffffffffu, a9,  off);
        a10 += __shfl_down_sync(0xffffffffu, a10, off);
        a11 += __shfl_down_sync(0xffffffffu, a11, off);
        a12 += __shfl_down_sync(0xffffffffu, a12, off);
        a13 += __shfl_down_sync(0xffffffffu, a13, off);
        a14 += __shfl_down_sync(0xffffffffu, a14, off);
        a15 += __shfl_down_sync(0xffffffffu, a15, off);
    }

    if (lane == 0) {
        const float ib = 1.0f / (float)B_DIM;
        g_Vr[(w * 16 + 0)  * F_DIM + f] = a0 * ib;  g_Vi[(w * 16 + 0)  * F_DIM + f] = 0.f;
        g_Vr[(w * 16 + 5)  * F_DIM + f] = a1 * ib;  g_Vi[(w * 16 + 5)  * F_DIM + f] = 0.f;
        g_Vr[(w * 16 + 10) * F_DIM + f] = a2 * ib;  g_Vi[(w * 16 + 10) * F_DIM + f] = 0.f;
        g_Vr[(w * 16 + 15) * F_DIM + f] = a3 * ib;  g_Vi[(w * 16 + 15) * F_DIM + f] = 0.f;
        g_Vr[(w * 16 + 1)  * F_DIM + f] = a4 * ib;  g_Vi[(w * 16 + 1)  * F_DIM + f] =  a5 * ib;
        g_Vr[(w * 16 + 4)  * F_DIM + f] = a4 * ib;  g_Vi[(w * 16 + 4)  * F_DIM + f] = -a5 * ib;
        g_Vr[(w * 16 + 2)  * F_DIM + f] = a6 * ib;  g_Vi[(w * 16 + 2)  * F_DIM + f] =  a7 * ib;
        g_Vr[(w * 16 + 8)  * F_DIM + f] = a6 * ib;  g_Vi[(w * 16 + 8)  * F_DIM + f] = -a7 * ib;
        g_Vr[(w * 16 + 3)  * F_DIM + f] = a8 * ib;  g_Vi[(w * 16 + 3)  * F_DIM + f] =  a9 * ib;
        g_Vr[(w * 16 + 12) * F_DIM + f] = a8 * ib;  g_Vi[(w * 16 + 12) * F_DIM + f] = -a9 * ib;
        g_Vr[(w * 16 + 6)  * F_DIM + f] = a10 * ib; g_Vi[(w * 16 + 6)  * F_DIM + f] =  a11 * ib;
        g_Vr[(w * 16 + 9)  * F_DIM + f] = a10 * ib; g_Vi[(w * 16 + 9)  * F_DIM + f] = -a11 * ib;
        g_Vr[(w * 16 + 7)  * F_DIM + f] = a12 * ib; g_Vi[(w * 16 + 7)  * F_DIM + f] =  a13 * ib;
        g_Vr[(w * 16 + 13) * F_DIM + f] = a12 * ib; g_Vi[(w * 16 + 13) * F_DIM + f] = -a13 * ib;
        g_Vr[(w * 16 + 11) * F_DIM + f] = a14 * ib; g_Vi[(w * 16 + 11) * F_DIM + f] =  a15 * ib;
        g_Vr[(w * 16 + 14) * F_DIM + f] = a14 * ib; g_Vi[(w * 16 + 14) * F_DIM + f] = -a15 * ib;
    }
}

// Sequential IP updates per frequency; one warp per block, shared columns.
static __global__ void k_ip(int compute_scale) {
    __shared__ float sWr[16][32], sWi[16][32];
    __shared__ float sVr[16][32], sVi[16][32];
    const int tid = threadIdx.x;          // 32 threads
    const int f = blockIdx.x * 32 + tid;
    if (f >= F_DIM) return;

#pragma unroll
    for (int e = 0; e < 16; e++) {
        sWr[e][tid] = g_Whr[f * 16 + e];
        sWi[e][tid] = g_Whi[f * 16 + e];
    }

    for (int k = 0; k < 4; k++) {
#pragma unroll
        for (int e = 0; e < 16; e++) {
            sVr[e][tid] = g_Vr[(k * 16 + e) * F_DIM + f];
            sVi[e][tid] = g_Vi[(k * 16 + e) * F_DIM + f];
        }
        float Mr[4][4], Mi[4][4];
#pragma unroll
        for (int i = 0; i < 4; i++)
#pragma unroll
            for (int j = 0; j < 4; j++) {
                float ar = 0.f, ai = 0.f;
#pragma unroll
                for (int c = 0; c < 4; c++) {
                    float wr = sWr[i * 4 + c][tid], wi = sWi[i * 4 + c][tid];
                    float vr = sVr[c * 4 + j][tid], vi = sVi[c * 4 + j][tid];
                    ar += wr * vr - wi * vi;
                    ai += wr * vi + wi * vr;
                }
                Mr[i][j] = ar;
                Mi[i][j] = ai;
            }
        float ur[4], ui[4];
#pragma unroll
        for (int e = 0; e < 4; e++) { ur[e] = (e == k) ? 1.f : 0.f; ui[e] = 0.f; }
        solve4(Mr, Mi, ur, ui);
        float q = 0.f;
#pragma unroll
        for (int c = 0; c < 4; c++) {
            float tr = 0.f, ti = 0.f;
#pragma unroll
            for (int j = 0; j < 4; j++) {
                float vr = sVr[c * 4 + j][tid], vi = sVi[c * 4 + j][tid];
                tr += vr * ur[j] - vi * ui[j];
                ti += vr * ui[j] + vi * ur[j];
            }
            q += ur[c] * tr + ui[c] * ti;
        }
        float invd = rsqrtf(q);
#pragma unroll
        for (int c = 0; c < 4; c++) {
            sWr[k * 4 + c][tid] =  ur[c] * invd;
            sWi[k * 4 + c][tid] = -ui[c] * invd;
        }
    }

#pragma unroll
    for (int e = 0; e < 16; e++) {
        g_Whr[f * 16 + e] = sWr[e][tid];
        g_Whi[f * 16 + e] = sWi[e][tid];
    }

    if (compute_scale) {
        float Ar[4][4], Ai[4][4], vr[4], vi[4];
#pragma unroll
        for (int i = 0; i < 4; i++)
#pragma unroll
            for (int j = 0; j < 4; j++) {
                Ar[i][j] = sWr[i * 4 + j][tid];
                Ai[i][j] = sWi[i * 4 + j][tid];
            }
#pragma unroll
        for (int e = 0; e < 4; e++) { vr[e] = (e == 0) ? 1.f : 0.f; vi[e] = 0.f; }
        solve4(Ar, Ai, vr, vi);
#pragma unroll
        for (int c = 0; c < 4; c++) {
            g_sclr[f * 4 + c] = vr[c];
            g_scli[f * 4 + c] = vi[c];
        }
    }
}

// out[s,f,b] = Re( (sum_c Wh[f,s,c] X[c,f,b]) * scale[f,s] )  — KFB floats.
static __global__ void k_out(float* __restrict__ out) {
    const int f  = blockIdx.x / NBB2;
    const int bb = blockIdx.x % NBB2;
    const int b  = bb * 256 + threadIdx.x;
    if (b >= B_DIM) return;

    const int base = f * B_DIM + b;
    float xr0 = g_Xr[base],          xi0 = g_Xi[base];
    float xr1 = g_Xr[base + FB],     xi1 = g_Xi[base + FB];
    float xr2 = g_Xr[base + 2 * FB], xi2 = g_Xi[base + 2 * FB];
    float xr3 = g_Xr[base + 3 * FB], xi3 = g_Xi[base + 3 * FB];

#pragma unroll
    for (int s = 0; s < 4; s++) {
        float w0r = g_Whr[f * 16 + s * 4 + 0], w0i = g_Whi[f * 16 + s * 4 + 0];
        float w1r = g_Whr[f * 16 + s * 4 + 1], w1i = g_Whi[f * 16 + s * 4 + 1];
        float w2r = g_Whr[f * 16 + s * 4 + 2], w2i = g_Whi[f * 16 + s * 4 + 2];
        float w3r = g_Whr[f * 16 + s * 4 + 3], w3i = g_Whi[f * 16 + s * 4 + 3];
        float yr = w0r * xr0 - w0i * xi0 + w1r * xr1 - w1i * xi1
                 + w2r * xr2 - w2i * xi2 + w3r * xr3 - w3i * xi3;
        float yi = w0r * xi0 + w0i * xr0 + w1r * xi1 + w1i * xr1
                 + w2r * xi2 + w2i * xr2 + w3r * xi3 + w3i * xr3;
        float scr = g_sclr[f * 4 + s];
        float sci = g_scli[f * 4 + s];
        out[s * FB + base] = yr * scr - yi * sci;   // real part only
    }
}

// ---------------- launch ----------------
extern "C" void kernel_launch(void* const* d_in, const int* in_sizes, int n_in,
                              void* d_out, int out_size) {
    if (n_in < 2) return;

    long long in0 = in_sizes[0], in1 = in_sizes[1];
    size_t b0 = (size_t)((in0 < KFB ? in0 : KFB)) * sizeof(float);
    size_t b1 = (size_t)((in1 < KFB ? in1 : KFB)) * sizeof(float);
    cudaError_t e0 = cudaMemcpyToSymbolAsync(g_Xr, d_in[0], b0, 0, cudaMemcpyDeviceToDevice);
    cudaError_t e1 = cudaMemcpyToSymbolAsync(g_Xi, d_in[1], b1, 0, cudaMemcpyDeviceToDevice);

    k_init<<<33, 256>>>();
    for (int it = 0; it < N_ITER; ++it) {
        k_demix<<<F_DIM * NBB2, 256>>>();
        k_phi<<<63, 256>>>();
        k_V<<<F_DIM, 128>>>();
        k_ip<<<17, 32>>>(it == N_ITER - 1 ? 1 : 0);
    }
    k_out<<<F_DIM * NBB2, 256>>>((float*)d_out);

    fprintf(stderr, "AUXDBG n_in=%d sizes=[%d,%d] out_size=%d memcpyIn=[%d,%d]\n",
            n_in, in_sizes[0], (n_in > 1) ? in_sizes[1] : -1, out_size,
            (int)e0, (int)e1);
    fflush(stderr);
}

// round 10
// speedup vs baseline: 2.0507x; 2.0507x over previous
#include <cuda_runtime.h>

// AuxIVA: K=4 sources, F=513 freqs, B=4000 frames, 5 iterations.
// d_in[0]=Xr (K,F,B) f32, d_in[1]=Xi (K,F,B) f32.
// Output: float32 (K,F,B) = real part of projected-back demixed signal.

#define K_DIM 4
#define F_DIM 513
#define B_DIM 4000
#define B4    (B_DIM / 4)          // 1000 float4 per (k,f) row
#define FB    (F_DIM * B_DIM)
#define FB4   (FB / 4)
#define KFB   (K_DIM * F_DIM * B_DIM)
#define N_ITER 5
#define FCH   57                   // f-chunks in k_demix
#define CHF   9                    // f per chunk (57*9 = 513)
#define NSPL  8                    // b-splits in k_V
#define NSLOT 32                   // warp slots per f in k_V (NSPL*4)

// ---------------- scratch ----------------
static __device__ float g_Whr[F_DIM * 16];             // [f][s][c]
static __device__ float g_Whi[F_DIM * 16];
static __device__ float g_part[FCH * K_DIM * B_DIM];   // [ch][k][b]
static __device__ float g_phi[K_DIM * B_DIM];          // 0.5/r, [k][b]
static __device__ float g_Vp[NSLOT * 64 * F_DIM];      // [slot][k*16+e][f]
static __device__ float g_V[64 * F_DIM];               // packed [k*16+e][f]
static __device__ float g_sclr[F_DIM * 4];             // [f][s]
static __device__ float g_scli[F_DIM * 4];

// Gauss-Jordan solve of 4x4 complex system, conditional-swap partial pivot.
static __device__ __forceinline__ void solve4(float Ar[4][4], float Ai[4][4],
                                              float ur[4], float ui[4]) {
#pragma unroll
    for (int j = 0; j < 4; j++) {
#pragma unroll
        for (int i = 0; i < 4; i++) {
            if (i > j) {
                float mj = Ar[j][j] * Ar[j][j] + Ai[j][j] * Ai[j][j];
                float mi = Ar[i][j] * Ar[i][j] + Ai[i][j] * Ai[i][j];
                if (mi > mj) {
#pragma unroll
                    for (int c = 0; c < 4; c++) {
                        float tr = Ar[j][c]; Ar[j][c] = Ar[i][c]; Ar[i][c] = tr;
                        float ti = Ai[j][c]; Ai[j][c] = Ai[i][c]; Ai[i][c] = ti;
                    }
                    float tr = ur[j]; ur[j] = ur[i]; ur[i] = tr;
                    float ti = ui[j]; ui[j] = ui[i]; ui[i] = ti;
                }
            }
        }
        float dr = Ar[j][j], di = Ai[j][j];
        float inv = 1.0f / (dr * dr + di * di);
        float pr = dr * inv, pi = -di * inv;
#pragma unroll
        for (int c = 0; c < 4; c++) {
            float ar = Ar[j][c], ai = Ai[j][c];
            Ar[j][c] = ar * pr - ai * pi;
            Ai[j][c] = ar * pi + ai * pr;
        }
        {
            float ar = ur[j], ai = ui[j];
            ur[j] = ar * pr - ai * pi;
            ui[j] = ar * pi + ai * pr;
        }
#pragma unroll
        for (int i = 0; i < 4; i++) {
            if (i != j) {
                float fr = Ar[i][j], fi = Ai[i][j];
#pragma unroll
                for (int c = 0; c < 4; c++) {
                    float ar = Ar[j][c], ai = Ai[j][c];
                    Ar[i][c] -= fr * ar - fi * ai;
                    Ai[i][c] -= fr * ai + fi * ar;
                }
                float ar = ur[j], ai = ui[j];
                ur[i] -= fr * ar - fi * ai;
                ui[i] -= fr * ai + fi * ar;
            }
        }
    }
}

// ---------------- kernels ----------------

static __global__ void k_init() {
    int i = blockIdx.x * blockDim.x + threadIdx.x;
    if (i < F_DIM * 16) {
        int rem = i & 15;
        g_Whr[i] = (rem == 0 || rem == 5 || rem == 10 || rem == 15) ? 1.f : 0.f;
        g_Whi[i] = 0.f;
    }
}

// part[ch][k][b] = sum over chunk's 9 f of |sum_c Wh[f,k,c] X[c,f,b]|^2
static __global__ void k_demix(const float4* __restrict__ Xr4,
                               const float4* __restrict__ Xi4) {
    const int ch  = blockIdx.x;                    // 0..56
    const int idx = blockIdx.y * 256 + threadIdx.x; // float4 index in b
    if (idx >= B4) return;

    float acc[4][4];                               // [s][sub-b]
#pragma unroll
    for (int s = 0; s < 4; s++)
#pragma unroll
        for (int u = 0; u < 4; u++) acc[s][u] = 0.f;

    const int f0 = ch * CHF;
    for (int fi = 0; fi < CHF; fi++) {
        const int f = f0 + fi;
        const int base4 = f * B4 + idx;
        float xr[4][4], xi[4][4];                  // [c][sub]
#pragma unroll
        for (int c = 0; c < 4; c++) {
            float4 tr = Xr4[c * FB4 + base4];
            float4 ti = Xi4[c * FB4 + base4];
            xr[c][0] = tr.x; xr[c][1] = tr.y; xr[c][2] = tr.z; xr[c][3] = tr.w;
            xi[c][0] = ti.x; xi[c][1] = ti.y; xi[c][2] = ti.z; xi[c][3] = ti.w;
        }
#pragma unroll
        for (int s = 0; s < 4; s++) {
            float wr[4], wi[4];
#pragma unroll
            for (int c = 0; c < 4; c++) {
                wr[c] = g_Whr[f * 16 + s * 4 + c];
                wi[c] = g_Whi[f * 16 + s * 4 + c];
            }
#pragma unroll
            for (int u = 0; u < 4; u++) {
                float yr = 0.f, yi = 0.f;
#pragma unroll
                for (int c = 0; c < 4; c++) {
                    yr += wr[c] * xr[c][u] - wi[c] * xi[c][u];
                    yi += wr[c] * xi[c][u] + wi[c] * xr[c][u];
                }
                acc[s][u] += yr * yr + yi * yi;
            }
        }
    }
    float4* P4 = (float4*)g_part;
#pragma unroll
    for (int s = 0; s < 4; s++) {
        float4 v;
        v.x = acc[s][0]; v.y = acc[s][1]; v.z = acc[s][2]; v.w = acc[s][3];
        P4[(ch * 4 + s) * B4 + idx] = v;
    }
}

// phi[k][b] = 0.5 / sqrt( sum_ch part[ch][k][b] )
static __global__ void k_phi() {
    int t = blockIdx.x * blockDim.x + threadIdx.x;     // (k*B4 + idx)
    if (t >= 4 * B4) return;
    const float4* P4 = (const float4*)g_part;
    const int k = t / B4, idx = t % B4;
    float4 s = make_float4(0.f, 0.f, 0.f, 0.f);
    for (int ch = 0; ch < FCH; ch++) {
        float4 v = P4[(ch * 4 + k) * B4 + idx];
        s.x += v.x; s.y += v.y; s.z += v.z; s.w += v.w;
    }
    float4 p;
    p.x = 0.5f * rsqrtf(s.x);
    p.y = 0.5f * rsqrtf(s.y);
    p.z = 0.5f * rsqrtf(s.z);
    p.w = 0.5f * rsqrtf(s.w);
    ((float4*)g_phi)[k * B4 + idx] = p;
}

// V partials: grid (F_DIM, NSPL), block 128. Each thread handles one float4
// of b (4 frames), computes the 16 Hermitian products ONCE, weights by all
// 4 phi's, warp-reduces, writes per-warp partials.
static __global__ void k_V(const float4* __restrict__ Xr4,
                           const float4* __restrict__ Xi4) {
    const int f = blockIdx.x;
    const int g = blockIdx.y * 128 + threadIdx.x;   // 0..1023 per f
    const int lane = threadIdx.x & 31;

    float acc[4][16];
#pragma unroll
    for (int k = 0; k < 4; k++)
#pragma unroll
        for (int e = 0; e < 16; e++) acc[k][e] = 0.f;

    if (g < B4) {
        const int base4 = f * B4 + g;
        float xr[4][4], xi[4][4];
#pragma unroll
        for (int c = 0; c < 4; c++) {
            float4 tr = Xr4[c * FB4 + base4];
            float4 ti = Xi4[c * FB4 + base4];
            xr[c][0] = tr.x; xr[c][1] = tr.y; xr[c][2] = tr.z; xr[c][3] = tr.w;
            xi[c][0] = ti.x; xi[c][1] = ti.y; xi[c][2] = ti.z; xi[c][3] = ti.w;
        }
        float ph[4][4];
#pragma unroll
        for (int k = 0; k < 4; k++) {
            float4 p = ((const float4*)g_phi)[k * B4 + g];
            ph[k][0] = p.x; ph[k][1] = p.y; ph[k][2] = p.z; ph[k][3] = p.w;
        }
#pragma unroll
        for (int u = 0; u < 4; u++) {
            float pr[16];
            pr[0]  = xr[0][u] * xr[0][u] + xi[0][u] * xi[0][u];
            pr[1]  = xr[1][u] * xr[1][u] + xi[1][u] * xi[1][u];
            pr[2]  = xr[2][u] * xr[2][u] + xi[2][u] * xi[2][u];
            pr[3]  = xr[3][u] * xr[3][u] + xi[3][u] * xi[3][u];
            pr[4]  = xr[0][u] * xr[1][u] + xi[0][u] * xi[1][u];
            pr[5]  = xi[0][u] * xr[1][u] - xr[0][u] * xi[1][u];
            pr[6]  = xr[0][u] * xr[2][u] + xi[0][u] * xi[2][u];
            pr[7]  = xi[0][u] * xr[2][u] - xr[0][u] * xi[2][u];
            pr[8]  = xr[0][u] * xr[3][u] + xi[0][u] * xi[3][u];
            pr[9]  = xi[0][u] * xr[3][u] - xr[0][u] * xi[3][u];
            pr[10] = xr[1][u] * xr[2][u] + xi[1][u] * xi[2][u];
            pr[11] = xi[1][u] * xr[2][u] - xr[1][u] * xi[2][u];
            pr[12] = xr[1][u] * xr[3][u] + xi[1][u] * xi[3][u];
            pr[13] = xi[1][u] * xr[3][u] - xr[1][u] * xi[3][u];
            pr[14] = xr[2][u] * xr[3][u] + xi[2][u] * xi[3][u];
            pr[15] = xi[2][u] * xr[3][u] - xr[2][u] * xi[3][u];
#pragma unroll
            for (int k = 0; k < 4; k++) {
                float p = ph[k][u];
#pragma unroll
                for (int e = 0; e < 16; e++)
                    acc[k][e] += p * pr[e];
            }
        }
    }

#pragma unroll
    for (int k = 0; k < 4; k++)
#pragma unroll
        for (int e = 0; e < 16; e++) {
#pragma unroll
            for (int off = 16; off > 0; off >>= 1)
                acc[k][e] += __shfl_down_sync(0xffffffffu, acc[k][e], off);
        }

    if (lane == 0) {
        const int slot = blockIdx.y * 4 + (threadIdx.x >> 5);   // 0..31
#pragma unroll
        for (int k = 0; k < 4; k++)
#pragma unroll
            for (int e = 0; e < 16; e++)
                g_Vp[(slot * 64 + k * 16 + e) * F_DIM + f] = acc[k][e];
    }
}

// Sum the 32 per-warp partials -> packed V (with 1/B scaling).
static __global__ void k_Vsum() {
    int t = blockIdx.x * blockDim.x + threadIdx.x;     // e64 * F_DIM + f
    if (t >= 64 * F_DIM) return;
    const int e = t / F_DIM, f = t % F_DIM;
    float s = 0.f;
#pragma unroll
    for (int slot = 0; slot < NSLOT; slot++)
        s += g_Vp[(slot * 64 + e) * F_DIM + f];
    g_V[e * F_DIM + f] = s * (1.0f / (float)B_DIM);
}

// IP updates per frequency; reads packed V, expands Hermitian in registers.
static __global__ void k_ip(int compute_scale) {
    __shared__ float sWr[16][32], sWi[16][32];
    const int tid = threadIdx.x;          // 32
    const int f = blockIdx.x * 32 + tid;
    if (f >= F_DIM) return;

#pragma unroll
    for (int e = 0; e < 16; e++) {
        sWr[e][tid] = g_Whr[f * 16 + e];
        sWi[e][tid] = g_Whi[f * 16 + e];
    }

    for (int k = 0; k < 4; k++) {
        float pk[16];
#pragma unroll
        for (int e = 0; e < 16; e++)
            pk[e] = g_V[(k * 16 + e) * F_DIM + f];
        // expand packed -> Hermitian Vk
        float Vr[4][4], Vi[4][4];
        Vr[0][0] = pk[0]; Vi[0][0] = 0.f;
        Vr[1][1] = pk[1]; Vi[1][1] = 0.f;
        Vr[2][2] = pk[2]; Vi[2][2] = 0.f;
        Vr[3][3] = pk[3]; Vi[3][3] = 0.f;
        Vr[0][1] = pk[4];  Vi[0][1] =  pk[5];  Vr[1][0] = pk[4];  Vi[1][0] = -pk[5];
        Vr[0][2] = pk[6];  Vi[0][2] =  pk[7];  Vr[2][0] = pk[6];  Vi[2][0] = -pk[7];
        Vr[0][3] = pk[8];  Vi[0][3] =  pk[9];  Vr[3][0] = pk[8];  Vi[3][0] = -pk[9];
        Vr[1][2] = pk[10]; Vi[1][2] =  pk[11]; Vr[2][1] = pk[10]; Vi[2][1] = -pk[11];
        Vr[1][3] = pk[12]; Vi[1][3] =  pk[13]; Vr[3][1] = pk[12]; Vi[3][1] = -pk[13];
        Vr[2][3] = pk[14]; Vi[2][3] =  pk[15]; Vr[3][2] = pk[14]; Vi[3][2] = -pk[15];

        float Mr[4][4], Mi[4][4];
#pragma unroll
        for (int i = 0; i < 4; i++)
#pragma unroll
            for (int j = 0; j < 4; j++) {
                float ar = 0.f, ai = 0.f;
#pragma unroll
                for (int c = 0; c < 4; c++) {
                    float wr = sWr[i * 4 + c][tid], wi = sWi[i * 4 + c][tid];
                    ar += wr * Vr[c][j] - wi * Vi[c][j];
                    ai += wr * Vi[c][j] + wi * Vr[c][j];
                }
                Mr[i][j] = ar;
                Mi[i][j] = ai;
            }
        float ur[4], ui[4];
#pragma unroll
        for (int e = 0; e < 4; e++) { ur[e] = (e == k) ? 1.f : 0.f; ui[e] = 0.f; }
        solve4(Mr, Mi, ur, ui);
        float q = 0.f;
#pragma unroll
        for (int c = 0; c < 4; c++) {
            float tr = 0.f, ti = 0.f;
#pragma unroll
            for (int j = 0; j < 4; j++) {
                tr += Vr[c][j] * ur[j] - Vi[c][j] * ui[j];
                ti += Vr[c][j] * ui[j] + Vi[c][j] * ur[j];
            }
            q += ur[c] * tr + ui[c] * ti;
        }
        float invd = rsqrtf(q);
#pragma unroll
        for (int c = 0; c < 4; c++) {
            sWr[k * 4 + c][tid] =  ur[c] * invd;
            sWi[k * 4 + c][tid] = -ui[c] * invd;
        }
    }

#pragma unroll
    for (int e = 0; e < 16; e++) {
        g_Whr[f * 16 + e] = sWr[e][tid];
        g_Whi[f * 16 + e] = sWi[e][tid];
    }

    if (compute_scale) {
        float Ar[4][4], Ai[4][4], vr[4], vi[4];
#pragma unroll
        for (int i = 0; i < 4; i++)
#pragma unroll
            for (int j = 0; j < 4; j++) {
                Ar[i][j] = sWr[i * 4 + j][tid];
                Ai[i][j] = sWi[i * 4 + j][tid];
            }
#pragma unroll
        for (int e = 0; e < 4; e++) { vr[e] = (e == 0) ? 1.f : 0.f; vi[e] = 0.f; }
        solve4(Ar, Ai, vr, vi);
#pragma unroll
        for (int c = 0; c < 4; c++) {
            g_sclr[f * 4 + c] = vr[c];
            g_scli[f * 4 + c] = vi[c];
        }
    }
}

// out[s,f,b] = Re( (sum_c Wh[f,s,c] X[c,f,b]) * scale[f,s] )
static __global__ void k_out(const float4* __restrict__ Xr4,
                             const float4* __restrict__ Xi4,
                             float4* __restrict__ out4) {
    const int f   = blockIdx.x;
    const int idx = blockIdx.y * 256 + threadIdx.x;
    if (idx >= B4) return;

    const int base4 = f * B4 + idx;
    float xr[4][4], xi[4][4];
#pragma unroll
    for (int c = 0; c < 4; c++) {
        float4 tr = Xr4[c * FB4 + base4];
        float4 ti = Xi4[c * FB4 + base4];
        xr[c][0] = tr.x; xr[c][1] = tr.y; xr[c][2] = tr.z; xr[c][3] = tr.w;
        xi[c][0] = ti.x; xi[c][1] = ti.y; xi[c][2] = ti.z; xi[c][3] = ti.w;
    }
#pragma unroll
    for (int s = 0; s < 4; s++) {
        float wr[4], wi[4];
#pragma unroll
        for (int c = 0; c < 4; c++) {
            wr[c] = g_Whr[f * 16 + s * 4 + c];
            wi[c] = g_Whi[f * 16 + s * 4 + c];
        }
        float scr = g_sclr[f * 4 + s];
        float sci = g_scli[f * 4 + s];
        float o[4];
#pragma unroll
        for (int u = 0; u < 4; u++) {
            float yr = 0.f, yi = 0.f;
#pragma unroll
            for (int c = 0; c < 4; c++) {
                yr += wr[c] * xr[c][u] - wi[c] * xi[c][u];
                yi += wr[c] * xi[c][u] + wi[c] * xr[c][u];
            }
            o[u] = yr * scr - yi * sci;
        }
        float4 v;
        v.x = o[0]; v.y = o[1]; v.z = o[2]; v.w = o[3];
        out4[s * FB4 + base4] = v;
    }
}

// ---------------- launch ----------------
extern "C" void kernel_launch(void* const* d_in, const int* in_sizes, int n_in,
                              void* d_out, int out_size) {
    if (n_in < 2) return;
    const float4* Xr4 = (const float4*)d_in[0];
    const float4* Xi4 = (const float4*)d_in[1];
    float4* out4 = (float4*)d_out;

    dim3 gD(FCH, 4);          // k_demix: 57 x 4 blocks, 256 thr
    dim3 gV(F_DIM, NSPL);     // k_V:     513 x 8 blocks, 128 thr
    dim3 gO(F_DIM, 4);        // k_out:   513 x 4 blocks, 256 thr

    k_init<<<33, 256>>>();
    for (int it = 0; it < N_ITER; ++it) {
        k_demix<<<gD, 256>>>(Xr4, Xi4);
        k_phi<<<16, 256>>>();
        k_V<<<gV, 128>>>(Xr4, Xi4);
        k_Vsum<<<129, 256>>>();
        k_ip<<<17, 32>>>(it == N_ITER - 1 ? 1 : 0);
    }
    k_out<<<gO, 256>>>(Xr4, Xi4, out4);
}